// round 1
// baseline (speedup 1.0000x reference)
#include <cuda_runtime.h>
#include <math.h>

#define NPTS     131072
#define HDIM     256
#define TILE_M   32
#define KCHUNK   32
#define NBLK     (NPTS / TILE_M)   // 4096
#define NTHREADS 256
#define GAMMA_F  (5.0f / 3.0f)

// Per-block partial sums of sum_r w_r * r^2 over the block's 32 points.
__device__ float g_partial[NBLK];

struct SmemLayout {
    float A[4][TILE_M][HDIM];   // activations: [0]=primal h, [1]=d/dx, [2]=d/dy, [3]=d/dt
    float Wc[KCHUNK][HDIM];     // staged weight chunk
    float W4s[HDIM][6];         // last-layer weights
    float OUT[4][TILE_M][6];    // preds + Jx + Jy + Jt
    float coords[TILE_M][3];
    float b4s[6];
};

// One hidden layer (256x256 + bias + tanh), propagating primal + 3 tangents.
// Thread t owns output column n = t. Vector-pairs share the staged W chunk.
__device__ __forceinline__ void gemm_layer(SmemLayout* s, const float* __restrict__ W,
                                           const float* __restrict__ b, int n) {
    #pragma unroll
    for (int vg = 0; vg < 2; vg++) {
        const int v0 = vg * 2, v1 = vg * 2 + 1;
        float acc0[TILE_M];
        float acc1[TILE_M];
        #pragma unroll
        for (int m = 0; m < TILE_M; m++) { acc0[m] = 0.f; acc1[m] = 0.f; }

        for (int kc = 0; kc < HDIM; kc += KCHUNK) {
            __syncthreads();   // previous Wc consumers done
            #pragma unroll
            for (int j = 0; j < (KCHUNK * HDIM) / NTHREADS; j++) {
                int i = n + j * NTHREADS;
                ((float*)s->Wc)[i] = W[kc * HDIM + i];
            }
            __syncthreads();   // Wc staged

            #pragma unroll 2
            for (int kk = 0; kk < KCHUNK; kk += 4) {
                const float w0 = s->Wc[kk + 0][n];
                const float w1 = s->Wc[kk + 1][n];
                const float w2 = s->Wc[kk + 2][n];
                const float w3 = s->Wc[kk + 3][n];
                #pragma unroll
                for (int m = 0; m < TILE_M; m++) {
                    const float4 a = *(const float4*)&s->A[v0][m][kc + kk];
                    acc0[m] = fmaf(a.x, w0, acc0[m]);
                    acc0[m] = fmaf(a.y, w1, acc0[m]);
                    acc0[m] = fmaf(a.z, w2, acc0[m]);
                    acc0[m] = fmaf(a.w, w3, acc0[m]);
                }
                #pragma unroll
                for (int m = 0; m < TILE_M; m++) {
                    const float4 a = *(const float4*)&s->A[v1][m][kc + kk];
                    acc1[m] = fmaf(a.x, w0, acc1[m]);
                    acc1[m] = fmaf(a.y, w1, acc1[m]);
                    acc1[m] = fmaf(a.z, w2, acc1[m]);
                    acc1[m] = fmaf(a.w, w3, acc1[m]);
                }
            }
        }
        __syncthreads();   // all reads of A complete before overwriting

        if (vg == 0) {
            const float bn = b[n];
            #pragma unroll
            for (int m = 0; m < TILE_M; m++) {
                float h = tanhf(acc0[m] + bn);
                s->A[0][m][n] = h;                       // new primal
                s->A[1][m][n] = (1.f - h * h) * acc1[m]; // tangent x
            }
        } else {
            #pragma unroll
            for (int m = 0; m < TILE_M; m++) {
                float h = s->A[0][m][n];                 // written by this same thread
                float sd = 1.f - h * h;
                s->A[2][m][n] = sd * acc0[m];            // tangent y
                s->A[3][m][n] = sd * acc1[m];            // tangent t
            }
        }
    }
    __syncthreads();
}

__device__ __forceinline__ float dE_of(const float* Jc, float rho, float vx, float vy,
                                       float Bx, float By, float ig) {
    return Jc[5] * ig + 0.5f * Jc[0] * (vx * vx + vy * vy)
         + rho * (vx * Jc[1] + vy * Jc[2]) + Bx * Jc[3] + By * Jc[4];
}
__device__ __forceinline__ float dG_of(const float* Jc, float vx, float vy, float Bx, float By) {
    return Jc[1] * By + vx * Jc[4] - Jc[2] * Bx - vy * Jc[3];
}
__device__ __forceinline__ float dD_of(const float* Jc, float vx, float vy, float Bx, float By) {
    return Jc[3] * vx + Bx * Jc[1] + Jc[4] * vy + By * Jc[2];
}

__global__ void __launch_bounds__(NTHREADS, 1)
mhd_kernel(const float* __restrict__ coords,
           const float* __restrict__ W1, const float* __restrict__ b1,
           const float* __restrict__ W2, const float* __restrict__ b2,
           const float* __restrict__ W3, const float* __restrict__ b3,
           const float* __restrict__ W4, const float* __restrict__ b4,
           const float* __restrict__ wts) {
    extern __shared__ char raw[];
    SmemLayout* s = (SmemLayout*)raw;
    const int n = threadIdx.x;          // output column owned by this thread
    const int base = blockIdx.x * TILE_M;

    // Stage coords tile, W4, b4
    if (n < TILE_M * 3) ((float*)s->coords)[n] = coords[base * 3 + n];
    #pragma unroll
    for (int j = 0; j < (HDIM * 6 + NTHREADS - 1) / NTHREADS; j++) {
        int i = n + j * NTHREADS;
        if (i < HDIM * 6) ((float*)s->W4s)[i] = W4[i];
    }
    if (n < 6) s->b4s[n] = b4[n];

    const float w1d0 = W1[n];
    const float w1d1 = W1[HDIM + n];
    const float w1d2 = W1[2 * HDIM + n];
    const float b1n  = b1[n];
    __syncthreads();

    // ---- Layer 1: 3 -> 256, tangents seeded by identity directions ----
    #pragma unroll 4
    for (int m = 0; m < TILE_M; m++) {
        float z = fmaf(s->coords[m][2], w1d2,
                  fmaf(s->coords[m][1], w1d1,
                  fmaf(s->coords[m][0], w1d0, b1n)));
        float h = tanhf(z);
        float sd = 1.f - h * h;
        s->A[0][m][n] = h;
        s->A[1][m][n] = sd * w1d0;   // d/dx
        s->A[2][m][n] = sd * w1d1;   // d/dy
        s->A[3][m][n] = sd * w1d2;   // d/dt
    }
    __syncthreads();

    // ---- Layers 2, 3: 256 -> 256 ----
    gemm_layer(s, W2, b2, n);
    gemm_layer(s, W3, b3, n);

    // ---- Layer 4: 256 -> 6, linear (tangents get no bias) ----
    for (int idx = n; idx < 4 * TILE_M * 6; idx += NTHREADS) {
        int v = idx / (TILE_M * 6);
        int r = idx % (TILE_M * 6);
        int m = r / 6, j = r % 6;
        float acc = (v == 0) ? s->b4s[j] : 0.f;
        #pragma unroll 8
        for (int k = 0; k < HDIM; k++)
            acc = fmaf(s->A[v][m][k], s->W4s[k][j], acc);
        s->OUT[v][m][j] = acc;
    }
    __syncthreads();

    // ---- Residuals + block reduction (warp 0, one lane per point) ----
    if (n < TILE_M) {
        const int m = n;
        const float* P  = s->OUT[0][m];
        const float* Jx = s->OUT[1][m];
        const float* Jy = s->OUT[2][m];
        const float* Jt = s->OUT[3][m];
        const float rho = P[0], vx = P[1], vy = P[2], Bx = P[3], By = P[4], Pp = P[5];
        const float ig = 1.f / (GAMMA_F - 1.f);

        const float dt_rho = Jt[0];
        const float dt_Bx  = Jt[3];
        const float dt_By  = Jt[4];
        const float dt_rhovx = dt_rho * vx + rho * Jt[1];
        const float dt_rhovy = dt_rho * vy + rho * Jt[2];

        const float dE_dx = dE_of(Jx, rho, vx, vy, Bx, By, ig);
        const float dE_dy = dE_of(Jy, rho, vx, vy, Bx, By, ig);
        const float dE_dt = dE_of(Jt, rho, vx, vy, Bx, By, ig);

        const float div_v = Jx[1] + Jy[2];
        const float div_B = Jx[3] + Jy[4];
        const float continuity = dt_rho + rho * div_v;

        const float dPm_dx = Jx[5] + Bx * Jx[3] + By * Jx[4];
        const float dPm_dy = Jy[5] + Bx * Jy[3] + By * Jy[4];
        const float momentum_x = dt_rhovx + dPm_dx - (Bx * Jx[3] + By * Jy[3]);
        const float momentum_y = dt_rhovy + dPm_dy - (Bx * Jx[4] + By * Jy[4]);

        const float induction_x = dt_Bx + dG_of(Jy, vx, vy, Bx, By);
        const float induction_y = dt_By - dG_of(Jx, vx, vy, Bx, By);

        const float Ee = Pp * ig + 0.5f * rho * (vx * vx + vy * vy) + 0.5f * (Bx * Bx + By * By);
        const float S  = Ee + Pp + 0.5f * (Bx * Bx + By * By);
        const float dS_dx = dE_dx + Jx[5] + Bx * Jx[3] + By * Jx[4];
        const float dS_dy = dE_dy + Jy[5] + Bx * Jy[3] + By * Jy[4];
        const float D = Bx * vx + By * vy;
        const float dFx_dx = dS_dx * vx + S * Jx[1] - dD_of(Jx, vx, vy, Bx, By) * Bx - D * Jx[3];
        const float dFy_dy = dS_dy * vy + S * Jy[2] - dD_of(Jy, vx, vy, Bx, By) * By - D * Jy[4];
        const float energy = dE_dt + dFx_dx + dFy_dy;

        float Sm = wts[0] * continuity * continuity
                 + wts[1] * momentum_x * momentum_x
                 + wts[2] * momentum_y * momentum_y
                 + wts[3] * induction_x * induction_x
                 + wts[4] * induction_y * induction_y
                 + wts[5] * energy * energy
                 + wts[6] * div_B * div_B;

        #pragma unroll
        for (int off = 16; off; off >>= 1)
            Sm += __shfl_down_sync(0xffffffffu, Sm, off);
        if (m == 0) g_partial[blockIdx.x] = Sm;
    }
}

__global__ void reduce_kernel(float* __restrict__ out) {
    __shared__ float sm[32];
    float sum = 0.f;
    for (int i = threadIdx.x; i < NBLK; i += blockDim.x) sum += g_partial[i];
    #pragma unroll
    for (int off = 16; off; off >>= 1) sum += __shfl_down_sync(0xffffffffu, sum, off);
    const int warp = threadIdx.x >> 5;
    if ((threadIdx.x & 31) == 0) sm[warp] = sum;
    __syncthreads();
    if (threadIdx.x < 32) {
        sum = (threadIdx.x < (int)(blockDim.x >> 5)) ? sm[threadIdx.x] : 0.f;
        #pragma unroll
        for (int off = 16; off; off >>= 1) sum += __shfl_down_sync(0xffffffffu, sum, off);
        if (threadIdx.x == 0) out[0] = sum / (float)NPTS;
    }
}

extern "C" void kernel_launch(void* const* d_in, const int* in_sizes, int n_in,
                              void* d_out, int out_size) {
    const float* coords = (const float*)d_in[0];
    const float* W1     = (const float*)d_in[1];
    const float* b1     = (const float*)d_in[2];
    const float* W2     = (const float*)d_in[3];
    const float* b2     = (const float*)d_in[4];
    const float* W3     = (const float*)d_in[5];
    const float* b3     = (const float*)d_in[6];
    const float* W4     = (const float*)d_in[7];
    const float* b4     = (const float*)d_in[8];
    const float* wts    = (const float*)d_in[9];

    const size_t smem_bytes = sizeof(SmemLayout);
    cudaFuncSetAttribute(mhd_kernel, cudaFuncAttributeMaxDynamicSharedMemorySize,
                         (int)smem_bytes);

    mhd_kernel<<<NBLK, NTHREADS, smem_bytes>>>(coords, W1, b1, W2, b2, W3, b3, W4, b4, wts);
    reduce_kernel<<<1, 1024>>>((float*)d_out);
}

// round 4
// speedup vs baseline: 2.8780x; 2.8780x over previous
#include <cuda_runtime.h>
#include <cuda_bf16.h>
#include <math.h>
#include <stdint.h>

#define NPTS     131072
#define HDIM     256
#define PTS      32              // points per CTA
#define NTH      512             // 16 warps
#define NBLK     (NPTS / PTS)    // 4096
#define AP       264             // A smem pitch (bf16 elems): 528B -> 4-bank phase shift
#define BP       40              // W smem pitch (bf16 elems): 80B  -> 20-bank phase shift
#define KCH      32              // K chunk
#define NCHUNK   (HDIM / KCH)    // 8
#define GAMMA_F  (5.0f / 3.0f)

__device__ __align__(16) __nv_bfloat16 g_Wt[2][2][HDIM * HDIM]; // [layer][hi/lo][n*256+k]
__device__ float g_partial[NBLK];

struct Smem {
    __nv_bfloat16 Ahi[128 * AP];            // 67584 B
    __nv_bfloat16 Alo[128 * AP];            // 67584 B
    __nv_bfloat16 Wb[2][2][HDIM * BP];      // 81920 B  [buf][hi/lo][n*40+k] ; reused as sdbuf
    float bias_s[HDIM];
    float W1s[3][HDIM];
    float W4Ts[6][HDIM];
    float OUT[4][32][6];
    float coords[32][3];
    float b4s[6];
};

// ---------------- asm helpers (all baseline sm_80+ PTX) ----------------
__device__ __forceinline__ uint32_t smem_u32(const void* p) {
    uint32_t a;
    asm("{ .reg .u64 t; cvta.to.shared.u64 t, %1; cvt.u32.u64 %0, t; }" : "=r"(a) : "l"(p));
    return a;
}
#define CP_ASYNC16(dst, src) \
    asm volatile("cp.async.cg.shared.global [%0], [%1], 16;" :: "r"(dst), "l"(src))
#define CP_COMMIT()  asm volatile("cp.async.commit_group;" ::: "memory")
#define CP_WAIT0()   asm volatile("cp.async.wait_group 0;" ::: "memory")

#define LDSM4(r0, r1, r2, r3, addr) \
    asm volatile("ldmatrix.sync.aligned.m8n8.x4.shared.b16 {%0,%1,%2,%3}, [%4];" \
                 : "=r"(r0), "=r"(r1), "=r"(r2), "=r"(r3) : "r"(addr))

#define MMA16816(d, a, b0, b1) \
    asm volatile("mma.sync.aligned.m16n8k16.row.col.f32.bf16.bf16.f32 " \
                 "{%0,%1,%2,%3}, {%4,%5,%6,%7}, {%8,%9}, {%0,%1,%2,%3};" \
                 : "+f"((d)[0]), "+f"((d)[1]), "+f"((d)[2]), "+f"((d)[3]) \
                 : "r"((a)[0]), "r"((a)[1]), "r"((a)[2]), "r"((a)[3]), \
                   "r"(b0), "r"(b1))

__device__ __forceinline__ void split_bf16(float v, __nv_bfloat16& hi, __nv_bfloat16& lo) {
    hi = __float2bfloat16(v);
    lo = __float2bfloat16(v - __bfloat162float(hi));
}

// ---------------- prep: W2/W3 fp32 [k][n] -> g_Wt[L][hi/lo][n][k] bf16 ----------------
__global__ void prep_kernel(const float* __restrict__ W2, const float* __restrict__ W3) {
    __shared__ float t[32][33];
    const float* W = blockIdx.z ? W3 : W2;
    const int tx = threadIdx.x, ty = threadIdx.y;
    const int bx = blockIdx.x, by = blockIdx.y, L = blockIdx.z;
    #pragma unroll
    for (int i = 0; i < 4; i++) {
        int lk = ty + i * 8;
        t[lk][tx] = W[(by * 32 + lk) * HDIM + bx * 32 + tx];
    }
    __syncthreads();
    #pragma unroll
    for (int i = 0; i < 4; i++) {
        int ln = ty + i * 8;
        int n = bx * 32 + ln;
        int k = by * 32 + tx;
        float w = t[tx][ln];
        __nv_bfloat16 hi, lo;
        split_bf16(w, hi, lo);
        g_Wt[L][0][n * HDIM + k] = hi;
        g_Wt[L][1][n * HDIM + k] = lo;
    }
}

// ---------------- main fused kernel ----------------
__global__ void __launch_bounds__(NTH, 1)
mhd_kernel(const float* __restrict__ coords,
           const float* __restrict__ W1, const float* __restrict__ b1,
           const float* __restrict__ W2, const float* __restrict__ b2,
           const float* __restrict__ W3, const float* __restrict__ b3,
           const float* __restrict__ W4, const float* __restrict__ b4,
           const float* __restrict__ wts) {
    extern __shared__ char raw[];
    Smem* s = (Smem*)raw;
    const int tid = threadIdx.x, wid = tid >> 5, lane = tid & 31;
    const int wm = wid >> 2, wn = wid & 3;      // 4x4 warp grid
    const int gid = lane >> 2, tig = lane & 3;  // mma fragment coords

    const uint32_t ahi_b = smem_u32(s->Ahi);
    const uint32_t alo_b = smem_u32(s->Alo);
    const uint32_t wb_b  = smem_u32(s->Wb);
    float* sdbuf = (float*)s->Wb;               // 32*AP floats, reused per-layer epilogue

    // ---- stage constants ----
    for (int i = tid; i < 3 * HDIM; i += NTH) ((float*)s->W1s)[i] = W1[i];
    for (int i = tid; i < 6 * HDIM; i += NTH) {
        int k = i / 6, j = i % 6;
        s->W4Ts[j][k] = W4[i];
    }
    for (int i = tid; i < HDIM; i += NTH) s->bias_s[i] = b1[i];
    if (tid < PTS * 3) ((float*)s->coords)[tid] = coords[blockIdx.x * PTS * 3 + tid];
    if (tid < 6) s->b4s[tid] = b4[tid];
    __syncthreads();

    // ---- layer 1: 3 -> 256, seed A (primal + 3 tangents) ----
    #pragma unroll
    for (int i = 0; i < 16; i++) {
        int idx = tid + i * NTH;                 // 0..8191
        int p = idx >> 8, n = idx & 255;
        float w0 = s->W1s[0][n], w1 = s->W1s[1][n], w2 = s->W1s[2][n];
        float z = fmaf(s->coords[p][2], w2,
                  fmaf(s->coords[p][1], w1,
                  fmaf(s->coords[p][0], w0, s->bias_s[n])));
        float h = tanhf(z);
        float sd = 1.f - h * h;
        __nv_bfloat16 hi, lo;
        split_bf16(h, hi, lo);
        s->Ahi[p * AP + n] = hi;  s->Alo[p * AP + n] = lo;
        split_bf16(sd * w0, hi, lo);
        s->Ahi[(32 + p) * AP + n] = hi;  s->Alo[(32 + p) * AP + n] = lo;
        split_bf16(sd * w1, hi, lo);
        s->Ahi[(64 + p) * AP + n] = hi;  s->Alo[(64 + p) * AP + n] = lo;
        split_bf16(sd * w2, hi, lo);
        s->Ahi[(96 + p) * AP + n] = hi;  s->Alo[(96 + p) * AP + n] = lo;
    }
    __syncthreads();

    // ---- layers 2 & 3: HMMA 3-pass split-bf16 ----
    const float* biases[2] = {b2, b3};
    for (int L = 0; L < 2; L++) {
        for (int i = tid; i < HDIM; i += NTH) s->bias_s[i] = biases[L][i];

        // chunk loader: 4 x 16B cp.async per thread
        auto load_chunk = [&](int buf, int kb) {
            #pragma unroll
            for (int i = 0; i < 4; i++) {
                int id = tid + i * NTH;          // 0..2047
                int h = id >> 10;                // hi/lo
                int r = id & 1023;
                int n = r >> 2, s8 = (r & 3) * 8;
                const __nv_bfloat16* src = &g_Wt[L][h][n * HDIM + kb + s8];
                uint32_t dst = wb_b + (uint32_t)(((buf * 2 + h) * (HDIM * BP)) + n * BP + s8) * 2u;
                CP_ASYNC16(dst, (const void*)src);
            }
            CP_COMMIT();
        };

        load_chunk(0, 0);

        float acc[2][8][4];
        #pragma unroll
        for (int mt = 0; mt < 2; mt++)
            #pragma unroll
            for (int nt = 0; nt < 8; nt++)
                #pragma unroll
                for (int e = 0; e < 4; e++) acc[mt][nt][e] = 0.f;

        for (int c = 0; c < NCHUNK; c++) {
            CP_WAIT0();
            __syncthreads();
            if (c + 1 < NCHUNK) load_chunk((c + 1) & 1, (c + 1) * KCH);
            const int buf = c & 1;
            const uint32_t wbuf_hi = wb_b + (uint32_t)((buf * 2 + 0) * (HDIM * BP)) * 2u;
            const uint32_t wbuf_lo = wb_b + (uint32_t)((buf * 2 + 1) * (HDIM * BP)) * 2u;

            #pragma unroll
            for (int kk2 = 0; kk2 < 2; kk2++) {      // two k16 steps per chunk
                const int kg = c * KCH + kk2 * 16;   // global k for A
                const int kl = kk2 * 16;             // local k for W chunk
                uint32_t a_hi[2][4], a_lo[2][4];
                #pragma unroll
                for (int mt = 0; mt < 2; mt++) {
                    int row = wm * 32 + mt * 16 + (lane & 15);
                    int col = kg + ((lane >> 4) << 3);
                    uint32_t off = (uint32_t)(row * AP + col) * 2u;
                    LDSM4(a_hi[mt][0], a_hi[mt][1], a_hi[mt][2], a_hi[mt][3], ahi_b + off);
                    LDSM4(a_lo[mt][0], a_lo[mt][1], a_lo[mt][2], a_lo[mt][3], alo_b + off);
                }
                #pragma unroll
                for (int nh = 0; nh < 2; nh++) {     // two n-halves to bound regs
                    uint32_t bh[2][4], bl[2][4];
                    #pragma unroll
                    for (int q = 0; q < 2; q++) {
                        int np = nh * 2 + q;
                        int nrow = wn * 64 + np * 16 + (lane & 7) + ((lane >> 4) << 3);
                        int kc = kl + (((lane >> 3) & 1) << 3);
                        uint32_t off = (uint32_t)(nrow * BP + kc) * 2u;
                        LDSM4(bh[q][0], bh[q][1], bh[q][2], bh[q][3], wbuf_hi + off);
                        LDSM4(bl[q][0], bl[q][1], bl[q][2], bl[q][3], wbuf_lo + off);
                    }
                    #pragma unroll
                    for (int mt = 0; mt < 2; mt++) {
                        #pragma unroll
                        for (int ntl = 0; ntl < 4; ntl++) {
                            int nt = nh * 4 + ntl;
                            int q = ntl >> 1, oct = ntl & 1;
                            uint32_t bh0 = bh[q][oct * 2], bh1 = bh[q][oct * 2 + 1];
                            uint32_t bl0 = bl[q][oct * 2], bl1 = bl[q][oct * 2 + 1];
                            MMA16816(acc[mt][nt], a_hi[mt], bh0, bh1);
                            MMA16816(acc[mt][nt], a_hi[mt], bl0, bl1);
                            MMA16816(acc[mt][nt], a_lo[mt], bh0, bh1);
                        }
                    }
                }
            }
        }
        __syncthreads();   // all mma done; Wb free -> sdbuf

        // ---- epilogue: primal warps tanh + publish sd; tangent warps scale ----
        if (wm == 0) {
            #pragma unroll
            for (int mt = 0; mt < 2; mt++) {
                #pragma unroll
                for (int nt = 0; nt < 8; nt++) {
                    int nb = wn * 64 + nt * 8 + 2 * tig;
                    #pragma unroll
                    for (int e = 0; e < 4; e++) {
                        int r = mt * 16 + gid + (e >> 1) * 8;
                        int n = nb + (e & 1);
                        float z = acc[mt][nt][e] + s->bias_s[n];
                        float h = tanhf(z);
                        float sd = 1.f - h * h;
                        __nv_bfloat16 hi, lo;
                        split_bf16(h, hi, lo);
                        s->Ahi[r * AP + n] = hi;
                        s->Alo[r * AP + n] = lo;
                        sdbuf[r * AP + n] = sd;
                    }
                }
            }
        }
        __syncthreads();
        if (wm > 0) {
            #pragma unroll
            for (int mt = 0; mt < 2; mt++) {
                #pragma unroll
                for (int nt = 0; nt < 8; nt++) {
                    int nb = wn * 64 + nt * 8 + 2 * tig;
                    #pragma unroll
                    for (int e = 0; e < 4; e++) {
                        int p = mt * 16 + gid + (e >> 1) * 8;    // point index
                        int r = wm * 32 + p;
                        int n = nb + (e & 1);
                        float v = acc[mt][nt][e] * sdbuf[p * AP + n];
                        __nv_bfloat16 hi, lo;
                        split_bf16(v, hi, lo);
                        s->Ahi[r * AP + n] = hi;
                        s->Alo[r * AP + n] = lo;
                    }
                }
            }
        }
        __syncthreads();
    }

    // ---- layer 4: 256 -> 6, k-split over 4 threads per row ----
    {
        int row = tid >> 2;          // 0..127
        int ks = tid & 3;
        float acc4[6] = {0.f, 0.f, 0.f, 0.f, 0.f, 0.f};
        #pragma unroll 8
        for (int k = ks * 64; k < ks * 64 + 64; k++) {
            float a = __bfloat162float(s->Ahi[row * AP + k]) +
                      __bfloat162float(s->Alo[row * AP + k]);
            #pragma unroll
            for (int j = 0; j < 6; j++)
                acc4[j] = fmaf(a, s->W4Ts[j][k], acc4[j]);
        }
        #pragma unroll
        for (int j = 0; j < 6; j++) {
            acc4[j] += __shfl_down_sync(0xffffffffu, acc4[j], 2, 4);
            acc4[j] += __shfl_down_sync(0xffffffffu, acc4[j], 1, 4);
        }
        if (ks == 0) {
            int v = row >> 5, m = row & 31;
            #pragma unroll
            for (int j = 0; j < 6; j++)
                s->OUT[v][m][j] = acc4[j] + ((v == 0) ? s->b4s[j] : 0.f);
        }
    }
    __syncthreads();

    // ---- residuals + block reduction (warp 0) ----
    if (wid == 0) {
        const int m = lane;
        const float* P  = s->OUT[0][m];
        const float* Jx = s->OUT[1][m];
        const float* Jy = s->OUT[2][m];
        const float* Jt = s->OUT[3][m];
        const float rho = P[0], vx = P[1], vy = P[2], Bx = P[3], By = P[4], Pp = P[5];
        const float ig = 1.f / (GAMMA_F - 1.f);

        const float dt_rho = Jt[0], dt_Bx = Jt[3], dt_By = Jt[4];
        const float dt_rhovx = dt_rho * vx + rho * Jt[1];
        const float dt_rhovy = dt_rho * vy + rho * Jt[2];

        #define DE(Jc) ((Jc)[5] * ig + 0.5f * (Jc)[0] * (vx * vx + vy * vy) \
                        + rho * (vx * (Jc)[1] + vy * (Jc)[2]) + Bx * (Jc)[3] + By * (Jc)[4])
        #define DG(Jc) ((Jc)[1] * By + vx * (Jc)[4] - (Jc)[2] * Bx - vy * (Jc)[3])
        #define DD(Jc) ((Jc)[3] * vx + Bx * (Jc)[1] + (Jc)[4] * vy + By * (Jc)[2])

        const float dE_dx = DE(Jx), dE_dy = DE(Jy), dE_dt = DE(Jt);
        const float div_v = Jx[1] + Jy[2];
        const float div_B = Jx[3] + Jy[4];
        const float continuity = dt_rho + rho * div_v;
        const float dPm_dx = Jx[5] + Bx * Jx[3] + By * Jx[4];
        const float dPm_dy = Jy[5] + Bx * Jy[3] + By * Jy[4];
        const float momentum_x = dt_rhovx + dPm_dx - (Bx * Jx[3] + By * Jy[3]);
        const float momentum_y = dt_rhovy + dPm_dy - (Bx * Jx[4] + By * Jy[4]);
        const float induction_x = dt_Bx + DG(Jy);
        const float induction_y = dt_By - DG(Jx);
        const float Ee = Pp * ig + 0.5f * rho * (vx * vx + vy * vy) + 0.5f * (Bx * Bx + By * By);
        const float S  = Ee + Pp + 0.5f * (Bx * Bx + By * By);
        const float dS_dx = dE_dx + Jx[5] + Bx * Jx[3] + By * Jx[4];
        const float dS_dy = dE_dy + Jy[5] + Bx * Jy[3] + By * Jy[4];
        const float D = Bx * vx + By * vy;
        const float dFx_dx = dS_dx * vx + S * Jx[1] - DD(Jx) * Bx - D * Jx[3];
        const float dFy_dy = dS_dy * vy + S * Jy[2] - DD(Jy) * By - D * Jy[4];
        const float energy = dE_dt + dFx_dx + dFy_dy;

        float Sm = wts[0] * continuity * continuity
                 + wts[1] * momentum_x * momentum_x
                 + wts[2] * momentum_y * momentum_y
                 + wts[3] * induction_x * induction_x
                 + wts[4] * induction_y * induction_y
                 + wts[5] * energy * energy
                 + wts[6] * div_B * div_B;

        #pragma unroll
        for (int off = 16; off; off >>= 1)
            Sm += __shfl_down_sync(0xffffffffu, Sm, off);
        if (m == 0) g_partial[blockIdx.x] = Sm;
    }
}

__global__ void reduce_kernel(float* __restrict__ out) {
    __shared__ float sm[32];
    float sum = 0.f;
    for (int i = threadIdx.x; i < NBLK; i += blockDim.x) sum += g_partial[i];
    #pragma unroll
    for (int off = 16; off; off >>= 1) sum += __shfl_down_sync(0xffffffffu, sum, off);
    const int warp = threadIdx.x >> 5;
    if ((threadIdx.x & 31) == 0) sm[warp] = sum;
    __syncthreads();
    if (threadIdx.x < 32) {
        sum = (threadIdx.x < (int)(blockDim.x >> 5)) ? sm[threadIdx.x] : 0.f;
        #pragma unroll
        for (int off = 16; off; off >>= 1) sum += __shfl_down_sync(0xffffffffu, sum, off);
        if (threadIdx.x == 0) out[0] = sum / (float)NPTS;
    }
}

extern "C" void kernel_launch(void* const* d_in, const int* in_sizes, int n_in,
                              void* d_out, int out_size) {
    const float* coords = (const float*)d_in[0];
    const float* W1     = (const float*)d_in[1];
    const float* b1     = (const float*)d_in[2];
    const float* W2     = (const float*)d_in[3];
    const float* b2     = (const float*)d_in[4];
    const float* W3     = (const float*)d_in[5];
    const float* b3     = (const float*)d_in[6];
    const float* W4     = (const float*)d_in[7];
    const float* b4     = (const float*)d_in[8];
    const float* wts    = (const float*)d_in[9];

    prep_kernel<<<dim3(8, 8, 2), dim3(32, 8)>>>(W2, W3);

    const size_t smem_bytes = sizeof(Smem);
    cudaFuncSetAttribute(mhd_kernel, cudaFuncAttributeMaxDynamicSharedMemorySize,
                         (int)smem_bytes);
    mhd_kernel<<<NBLK, NTH, smem_bytes>>>(coords, W1, b1, W2, b2, W3, b3, W4, b4, wts);
    reduce_kernel<<<1, 1024>>>((float*)d_out);
}

// round 5
// speedup vs baseline: 2.8878x; 1.0034x over previous
#include <cuda_runtime.h>
#include <cuda_bf16.h>
#include <math.h>
#include <stdint.h>

#define NPTS     131072
#define HDIM     256
#define PTS      32              // points per CTA
#define NTH      512             // 16 warps
#define NBLK     (NPTS / PTS)    // 4096
#define AP       264             // A smem pitch (bf16): 528B -> conflict-free ldmatrix
#define BP       40              // W smem pitch (bf16): 80B  -> conflict-free ldmatrix
#define KCH      32              // K chunk
#define NCHUNK   (HDIM / KCH)    // 8
#define GAMMA_F  (5.0f / 3.0f)

__device__ __align__(16) __nv_bfloat16 g_Wt[2][2][HDIM * HDIM]; // [layer][hi/lo][n*256+k]
__device__ float g_partial[NBLK];
__device__ unsigned int g_count = 0;

struct Smem {
    __nv_bfloat16 Ahi[128 * AP];            // 67584 B
    __nv_bfloat16 Alo[128 * AP];            // 67584 B
    __nv_bfloat16 Wb[2][2][HDIM * BP];      // 81920 B ; reused as sdbuf in epilogue
    float bias_s[HDIM];
    float W1s[3][HDIM];
    float W4Ts[6][HDIM];
    float OUT[4][32][6];
    float coords[32][3];
    float b4s[6];
    int   done;
};

// ---------------- asm helpers (baseline sm_80+ PTX only) ----------------
__device__ __forceinline__ uint32_t smem_u32(const void* p) {
    uint32_t a;
    asm("{ .reg .u64 t; cvta.to.shared.u64 t, %1; cvt.u32.u64 %0, t; }" : "=r"(a) : "l"(p));
    return a;
}
#define CP_ASYNC16(dst, src) \
    asm volatile("cp.async.cg.shared.global [%0], [%1], 16;" :: "r"(dst), "l"(src))
#define CP_COMMIT()  asm volatile("cp.async.commit_group;" ::: "memory")
#define CP_WAIT0()   asm volatile("cp.async.wait_group 0;" ::: "memory")

#define LDSM4(r0, r1, r2, r3, addr) \
    asm volatile("ldmatrix.sync.aligned.m8n8.x4.shared.b16 {%0,%1,%2,%3}, [%4];" \
                 : "=r"(r0), "=r"(r1), "=r"(r2), "=r"(r3) : "r"(addr))

#define MMA16816(d, a, b0, b1) \
    asm volatile("mma.sync.aligned.m16n8k16.row.col.f32.bf16.bf16.f32 " \
                 "{%0,%1,%2,%3}, {%4,%5,%6,%7}, {%8,%9}, {%0,%1,%2,%3};" \
                 : "+f"((d)[0]), "+f"((d)[1]), "+f"((d)[2]), "+f"((d)[3]) \
                 : "r"((a)[0]), "r"((a)[1]), "r"((a)[2]), "r"((a)[3]), \
                   "r"(b0), "r"(b1))

__device__ __forceinline__ void split_bf16(float v, __nv_bfloat16& hi, __nv_bfloat16& lo) {
    hi = __float2bfloat16(v);
    lo = __float2bfloat16(v - __bfloat162float(hi));
}
// pack two consecutive values into bf16x2 hi & lo words
__device__ __forceinline__ void split2_store(__nv_bfloat16* hi_p, __nv_bfloat16* lo_p,
                                             float v0, float v1) {
    __nv_bfloat162 h2 = __floats2bfloat162_rn(v0, v1);
    __nv_bfloat162 l2 = __floats2bfloat162_rn(v0 - __bfloat162float(h2.x),
                                              v1 - __bfloat162float(h2.y));
    *(__nv_bfloat162*)hi_p = h2;
    *(__nv_bfloat162*)lo_p = l2;
}

// ---------------- prep: W2/W3 fp32 [k][n] -> g_Wt[L][hi/lo][n][k] bf16 ----------------
__global__ void prep_kernel(const float* __restrict__ W2, const float* __restrict__ W3) {
    __shared__ float t[32][33];
    const float* W = blockIdx.z ? W3 : W2;
    const int tx = threadIdx.x, ty = threadIdx.y;
    const int bx = blockIdx.x, by = blockIdx.y, L = blockIdx.z;
    #pragma unroll
    for (int i = 0; i < 4; i++) {
        int lk = ty + i * 8;
        t[lk][tx] = W[(by * 32 + lk) * HDIM + bx * 32 + tx];
    }
    __syncthreads();
    #pragma unroll
    for (int i = 0; i < 4; i++) {
        int ln = ty + i * 8;
        int n = bx * 32 + ln;
        int k = by * 32 + tx;
        float w = t[tx][ln];
        __nv_bfloat16 hi, lo;
        split_bf16(w, hi, lo);
        g_Wt[L][0][n * HDIM + k] = hi;
        g_Wt[L][1][n * HDIM + k] = lo;
    }
}

// ---------------- main fused kernel ----------------
__global__ void __launch_bounds__(NTH, 1)
mhd_kernel(const float* __restrict__ coords,
           const float* __restrict__ W1, const float* __restrict__ b1,
           const float* __restrict__ b2, const float* __restrict__ b3,
           const float* __restrict__ W4, const float* __restrict__ b4,
           const float* __restrict__ wts, float* __restrict__ out) {
    extern __shared__ char raw[];
    Smem* s = (Smem*)raw;
    const int tid = threadIdx.x, wid = tid >> 5, lane = tid & 31;
    const int wm = wid >> 2, wn = wid & 3;      // 4x4 warp grid
    const int gid = lane >> 2, tig = lane & 3;  // mma fragment coords

    const uint32_t ahi_b = smem_u32(s->Ahi);
    const uint32_t alo_b = smem_u32(s->Alo);
    const uint32_t wb_b  = smem_u32(s->Wb);
    float* sdbuf = (float*)s->Wb;               // 32*AP floats, epilogue reuse

    // ---- stage constants ----
    for (int i = tid; i < 3 * HDIM; i += NTH) ((float*)s->W1s)[i] = W1[i];
    for (int i = tid; i < 6 * HDIM; i += NTH) {
        int k = i / 6, j = i % 6;
        s->W4Ts[j][k] = W4[i];
    }
    for (int i = tid; i < HDIM; i += NTH) s->bias_s[i] = b1[i];
    if (tid < PTS * 3) ((float*)s->coords)[tid] = coords[blockIdx.x * PTS * 3 + tid];
    if (tid < 6) s->b4s[tid] = b4[tid];
    __syncthreads();

    // ---- layer 1: 3 -> 256, seed A (primal + 3 tangents), 2 cols per thread ----
    #pragma unroll
    for (int i = 0; i < 8; i++) {
        int idx = tid + i * NTH;                 // 0..4095
        int p = idx >> 7, n = (idx & 127) * 2;
        float w00 = s->W1s[0][n], w01 = s->W1s[0][n + 1];
        float w10 = s->W1s[1][n], w11 = s->W1s[1][n + 1];
        float w20 = s->W1s[2][n], w21 = s->W1s[2][n + 1];
        float c0 = s->coords[p][0], c1 = s->coords[p][1], c2 = s->coords[p][2];
        float z0 = fmaf(c2, w20, fmaf(c1, w10, fmaf(c0, w00, s->bias_s[n])));
        float z1 = fmaf(c2, w21, fmaf(c1, w11, fmaf(c0, w01, s->bias_s[n + 1])));
        float h0 = tanhf(z0), h1 = tanhf(z1);
        float sd0 = 1.f - h0 * h0, sd1 = 1.f - h1 * h1;
        split2_store(&s->Ahi[p * AP + n],        &s->Alo[p * AP + n],        h0,        h1);
        split2_store(&s->Ahi[(32 + p) * AP + n], &s->Alo[(32 + p) * AP + n], sd0 * w00, sd1 * w01);
        split2_store(&s->Ahi[(64 + p) * AP + n], &s->Alo[(64 + p) * AP + n], sd0 * w10, sd1 * w11);
        split2_store(&s->Ahi[(96 + p) * AP + n], &s->Alo[(96 + p) * AP + n], sd0 * w20, sd1 * w21);
    }
    __syncthreads();

    // precomputed ldmatrix lane address components
    const uint32_t a_row = (uint32_t)(wm * 32 + (lane & 15));
    const uint32_t a_colsel = (uint32_t)((lane >> 4) << 3);
    const uint32_t b_nrow_base = (uint32_t)(wn * 64 + (lane & 7) + ((lane >> 4) << 3));
    const uint32_t b_ksel = (uint32_t)(((lane >> 3) & 1) << 3);

    // ---- layers 2 & 3: HMMA 3-sweep split-bf16 ----
    const float* biases[2] = {b2, b3};
    for (int L = 0; L < 2; L++) {
        for (int i = tid; i < HDIM; i += NTH) s->bias_s[i] = biases[L][i];

        auto load_chunk = [&](int buf, int kb) {
            #pragma unroll
            for (int i = 0; i < 4; i++) {
                int id = tid + i * NTH;          // 0..2047
                int h = id >> 10;                // hi/lo
                int r = id & 1023;
                int n = r >> 2, s8 = (r & 3) * 8;
                const __nv_bfloat16* src = &g_Wt[L][h][n * HDIM + kb + s8];
                uint32_t dst = wb_b + (uint32_t)(((buf * 2 + h) * (HDIM * BP)) + n * BP + s8) * 2u;
                CP_ASYNC16(dst, (const void*)src);
            }
            CP_COMMIT();
        };

        load_chunk(0, 0);

        float acc[2][8][4];
        #pragma unroll
        for (int mt = 0; mt < 2; mt++)
            #pragma unroll
            for (int nt = 0; nt < 8; nt++)
                #pragma unroll
                for (int e = 0; e < 4; e++) acc[mt][nt][e] = 0.f;

        for (int c = 0; c < NCHUNK; c++) {
            CP_WAIT0();
            __syncthreads();
            if (c + 1 < NCHUNK) load_chunk((c + 1) & 1, (c + 1) * KCH);
            const int buf = c & 1;
            const uint32_t wbuf_hi = wb_b + (uint32_t)((buf * 2 + 0) * (HDIM * BP)) * 2u;
            const uint32_t wbuf_lo = wb_b + (uint32_t)((buf * 2 + 1) * (HDIM * BP)) * 2u;

            #pragma unroll
            for (int kk2 = 0; kk2 < 2; kk2++) {
                const uint32_t a_off = (uint32_t)(a_row * AP + c * KCH + kk2 * 16 + a_colsel) * 2u;
                const uint32_t b_k   = (uint32_t)(kk2 * 16 + b_ksel);

                // ---- sweep 1: a_hi x b_hi ----
                {
                    uint32_t ah[2][4];
                    LDSM4(ah[0][0], ah[0][1], ah[0][2], ah[0][3], ahi_b + a_off);
                    LDSM4(ah[1][0], ah[1][1], ah[1][2], ah[1][3], ahi_b + a_off + 16u * AP * 2u);
                    #pragma unroll
                    for (int nh = 0; nh < 2; nh++) {
                        uint32_t bh[2][4];
                        #pragma unroll
                        for (int q = 0; q < 2; q++) {
                            uint32_t off = ((b_nrow_base + (uint32_t)((nh * 2 + q) * 16)) * BP + b_k) * 2u;
                            LDSM4(bh[q][0], bh[q][1], bh[q][2], bh[q][3], wbuf_hi + off);
                        }
                        #pragma unroll
                        for (int mt = 0; mt < 2; mt++)
                            #pragma unroll
                            for (int ntl = 0; ntl < 4; ntl++)
                                MMA16816(acc[mt][nh * 4 + ntl], ah[mt],
                                         bh[ntl >> 1][(ntl & 1) * 2], bh[ntl >> 1][(ntl & 1) * 2 + 1]);
                    }
                    // ---- sweep 2: a_hi x b_lo ----
                    #pragma unroll
                    for (int nh = 0; nh < 2; nh++) {
                        uint32_t bl[2][4];
                        #pragma unroll
                        for (int q = 0; q < 2; q++) {
                            uint32_t off = ((b_nrow_base + (uint32_t)((nh * 2 + q) * 16)) * BP + b_k) * 2u;
                            LDSM4(bl[q][0], bl[q][1], bl[q][2], bl[q][3], wbuf_lo + off);
                        }
                        #pragma unroll
                        for (int mt = 0; mt < 2; mt++)
                            #pragma unroll
                            for (int ntl = 0; ntl < 4; ntl++)
                                MMA16816(acc[mt][nh * 4 + ntl], ah[mt],
                                         bl[ntl >> 1][(ntl & 1) * 2], bl[ntl >> 1][(ntl & 1) * 2 + 1]);
                    }
                }
                // ---- sweep 3: a_lo x b_hi ----
                {
                    uint32_t al[2][4];
                    LDSM4(al[0][0], al[0][1], al[0][2], al[0][3], alo_b + a_off);
                    LDSM4(al[1][0], al[1][1], al[1][2], al[1][3], alo_b + a_off + 16u * AP * 2u);
                    #pragma unroll
                    for (int nh = 0; nh < 2; nh++) {
                        uint32_t bh[2][4];
                        #pragma unroll
                        for (int q = 0; q < 2; q++) {
                            uint32_t off = ((b_nrow_base + (uint32_t)((nh * 2 + q) * 16)) * BP + b_k) * 2u;
                            LDSM4(bh[q][0], bh[q][1], bh[q][2], bh[q][3], wbuf_hi + off);
                        }
                        #pragma unroll
                        for (int mt = 0; mt < 2; mt++)
                            #pragma unroll
                            for (int ntl = 0; ntl < 4; ntl++)
                                MMA16816(acc[mt][nh * 4 + ntl], al[mt],
                                         bh[ntl >> 1][(ntl & 1) * 2], bh[ntl >> 1][(ntl & 1) * 2 + 1]);
                    }
                }
            }
        }
        __syncthreads();   // mma done; Wb free -> sdbuf

        // ---- epilogue ----
        if (wm == 0) {
            #pragma unroll
            for (int mt = 0; mt < 2; mt++) {
                #pragma unroll
                for (int nt = 0; nt < 8; nt++) {
                    int nb = wn * 64 + nt * 8 + 2 * tig;
                    #pragma unroll
                    for (int eh = 0; eh < 2; eh++) {
                        int r = mt * 16 + gid + eh * 8;
                        float z0 = acc[mt][nt][eh * 2]     + s->bias_s[nb];
                        float z1 = acc[mt][nt][eh * 2 + 1] + s->bias_s[nb + 1];
                        float h0 = tanhf(z0), h1 = tanhf(z1);
                        split2_store(&s->Ahi[r * AP + nb], &s->Alo[r * AP + nb], h0, h1);
                        sdbuf[r * AP + nb]     = 1.f - h0 * h0;
                        sdbuf[r * AP + nb + 1] = 1.f - h1 * h1;
                    }
                }
            }
        }
        __syncthreads();
        if (wm > 0) {
            #pragma unroll
            for (int mt = 0; mt < 2; mt++) {
                #pragma unroll
                for (int nt = 0; nt < 8; nt++) {
                    int nb = wn * 64 + nt * 8 + 2 * tig;
                    #pragma unroll
                    for (int eh = 0; eh < 2; eh++) {
                        int p = mt * 16 + gid + eh * 8;
                        int r = wm * 32 + p;
                        float v0 = acc[mt][nt][eh * 2]     * sdbuf[p * AP + nb];
                        float v1 = acc[mt][nt][eh * 2 + 1] * sdbuf[p * AP + nb + 1];
                        split2_store(&s->Ahi[r * AP + nb], &s->Alo[r * AP + nb], v0, v1);
                    }
                }
            }
        }
        __syncthreads();
    }

    // ---- layer 4: 256 -> 6, k-split over 4 threads per row ----
    {
        int row = tid >> 2;
        int ks = tid & 3;
        float acc4[6] = {0.f, 0.f, 0.f, 0.f, 0.f, 0.f};
        #pragma unroll 8
        for (int k = ks * 64; k < ks * 64 + 64; k++) {
            float a = __bfloat162float(s->Ahi[row * AP + k]) +
                      __bfloat162float(s->Alo[row * AP + k]);
            #pragma unroll
            for (int j = 0; j < 6; j++)
                acc4[j] = fmaf(a, s->W4Ts[j][k], acc4[j]);
        }
        #pragma unroll
        for (int j = 0; j < 6; j++) {
            acc4[j] += __shfl_down_sync(0xffffffffu, acc4[j], 2, 4);
            acc4[j] += __shfl_down_sync(0xffffffffu, acc4[j], 1, 4);
        }
        if (ks == 0) {
            int v = row >> 5, m = row & 31;
            #pragma unroll
            for (int j = 0; j < 6; j++)
                s->OUT[v][m][j] = acc4[j] + ((v == 0) ? s->b4s[j] : 0.f);
        }
    }
    __syncthreads();

    // ---- residuals + block reduction (warp 0) ----
    if (wid == 0) {
        const int m = lane;
        const float* P  = s->OUT[0][m];
        const float* Jx = s->OUT[1][m];
        const float* Jy = s->OUT[2][m];
        const float* Jt = s->OUT[3][m];
        const float rho = P[0], vx = P[1], vy = P[2], Bx = P[3], By = P[4], Pp = P[5];
        const float ig = 1.f / (GAMMA_F - 1.f);

        const float dt_rho = Jt[0], dt_Bx = Jt[3], dt_By = Jt[4];
        const float dt_rhovx = dt_rho * vx + rho * Jt[1];
        const float dt_rhovy = dt_rho * vy + rho * Jt[2];

        #define DE(Jc) ((Jc)[5] * ig + 0.5f * (Jc)[0] * (vx * vx + vy * vy) \
                        + rho * (vx * (Jc)[1] + vy * (Jc)[2]) + Bx * (Jc)[3] + By * (Jc)[4])
        #define DG(Jc) ((Jc)[1] * By + vx * (Jc)[4] - (Jc)[2] * Bx - vy * (Jc)[3])
        #define DD(Jc) ((Jc)[3] * vx + Bx * (Jc)[1] + (Jc)[4] * vy + By * (Jc)[2])

        const float dE_dx = DE(Jx), dE_dy = DE(Jy), dE_dt = DE(Jt);
        const float div_v = Jx[1] + Jy[2];
        const float div_B = Jx[3] + Jy[4];
        const float continuity = dt_rho + rho * div_v;
        const float dPm_dx = Jx[5] + Bx * Jx[3] + By * Jx[4];
        const float dPm_dy = Jy[5] + Bx * Jy[3] + By * Jy[4];
        const float momentum_x = dt_rhovx + dPm_dx - (Bx * Jx[3] + By * Jy[3]);
        const float momentum_y = dt_rhovy + dPm_dy - (Bx * Jx[4] + By * Jy[4]);
        const float induction_x = dt_Bx + DG(Jy);
        const float induction_y = dt_By - DG(Jx);
        const float Ee = Pp * ig + 0.5f * rho * (vx * vx + vy * vy) + 0.5f * (Bx * Bx + By * By);
        const float S  = Ee + Pp + 0.5f * (Bx * Bx + By * By);
        const float dS_dx = dE_dx + Jx[5] + Bx * Jx[3] + By * Jx[4];
        const float dS_dy = dE_dy + Jy[5] + Bx * Jy[3] + By * Jy[4];
        const float D = Bx * vx + By * vy;
        const float dFx_dx = dS_dx * vx + S * Jx[1] - DD(Jx) * Bx - D * Jx[3];
        const float dFy_dy = dS_dy * vy + S * Jy[2] - DD(Jy) * By - D * Jy[4];
        const float energy = dE_dt + dFx_dx + dFy_dy;

        float Sm = wts[0] * continuity * continuity
                 + wts[1] * momentum_x * momentum_x
                 + wts[2] * momentum_y * momentum_y
                 + wts[3] * induction_x * induction_x
                 + wts[4] * induction_y * induction_y
                 + wts[5] * energy * energy
                 + wts[6] * div_B * div_B;

        #pragma unroll
        for (int off = 16; off; off >>= 1)
            Sm += __shfl_down_sync(0xffffffffu, Sm, off);
        if (m == 0) g_partial[blockIdx.x] = Sm;
    }

    // ---- last-block final reduction (deterministic) ----
    if (tid == 0) {
        __threadfence();
        unsigned int ticket = atomicAdd(&g_count, 1u);
        s->done = (ticket == NBLK - 1) ? 1 : 0;
    }
    __syncthreads();
    if (s->done) {
        __threadfence();
        float sum = 0.f;
        for (int i = tid; i < NBLK; i += NTH) sum += g_partial[i];
        #pragma unroll
        for (int off = 16; off; off >>= 1) sum += __shfl_down_sync(0xffffffffu, sum, off);
        __shared__ float warp_s[16];
        if (lane == 0) warp_s[wid] = sum;
        __syncthreads();
        if (wid == 0) {
            sum = (lane < 16) ? warp_s[lane] : 0.f;
            #pragma unroll
            for (int off = 8; off; off >>= 1) sum += __shfl_down_sync(0xffffffffu, sum, off);
            if (lane == 0) {
                out[0] = sum / (float)NPTS;
                g_count = 0;   // reset for next call
            }
        }
    }
}

extern "C" void kernel_launch(void* const* d_in, const int* in_sizes, int n_in,
                              void* d_out, int out_size) {
    const float* coords = (const float*)d_in[0];
    const float* W1     = (const float*)d_in[1];
    const float* b1     = (const float*)d_in[2];
    const float* W2     = (const float*)d_in[3];
    const float* b2     = (const float*)d_in[4];
    const float* W3     = (const float*)d_in[5];
    const float* b3     = (const float*)d_in[6];
    const float* W4     = (const float*)d_in[7];
    const float* b4     = (const float*)d_in[8];
    const float* wts    = (const float*)d_in[9];

    prep_kernel<<<dim3(8, 8, 2), dim3(32, 8)>>>(W2, W3);

    const size_t smem_bytes = sizeof(Smem);
    cudaFuncSetAttribute(mhd_kernel, cudaFuncAttributeMaxDynamicSharedMemorySize,
                         (int)smem_bytes);
    mhd_kernel<<<NBLK, NTH, smem_bytes>>>(coords, W1, b1, b2, b3, W4, b4, wts,
                                          (float*)d_out);
}